// round 16
// baseline (speedup 1.0000x reference)
#include <cuda_runtime.h>
#include <cuda_fp16.h>
#include <cstdint>

// ============================================================================
// LoRALayer: out[16384,4096] = x[16384,4096] @ W_eff^T + bias
//   W_eff[o,d] = weight[o,d] + sum_r A[d,r]*B[r,o]
// sm_103 (non-'a' PTX): legacy mma.sync fp16 HMMA, fp32 accum, 1 pass.
// R16: R15 (best) with ONE isolated change: the 16-deep iter-start cp.async
// burst is spread as 4 cp16 per kc, issued AFTER each kc's first MMA group.
// Barrier/wait structure identical to R11/R15 (commit at kc3, wait0+sync at
// iter end). Tests whether R12's regression was the barrier move (likely)
// or the spread loads.
// ============================================================================

#define DINL __device__ __forceinline__

constexpr int M_DIM = 16384;
constexpr int N_DIM = 4096;
constexpr int K_DIM = 4096;
constexpr int RANK  = 16;

constexpr int BM = 128;
constexpr int BN = 128;
constexpr int BK = 64;
constexpr int NKI = K_DIM / BK;           // 64 k-iterations
constexpr int STAGES = 3;

// per-stage smem (fp16, 128B rows): XH[128][64] WH[128][64]
constexpr int OFF_XH = 0;
constexpr int OFF_WH = 16384;
constexpr int STAGE_B = 32768;
constexpr int SMEM_BYTES = STAGES * STAGE_B;   // 98304 (occ 2 ok)

constexpr int SPLIT_BLOCKS = (int)(((size_t)M_DIM * K_DIM) / 8 / 256);  // 32768
constexpr int BUILD_BLOCKS = (K_DIM / 64) * (N_DIM / 256);              // 1024

constexpr unsigned long long PHASE_DELAY = 1280;

// ---------------- scratch (device globals; no runtime allocation) ----------
__device__ __half g_xh[(size_t)M_DIM * K_DIM];
__device__ __half g_wh[(size_t)N_DIM * K_DIM];

// ---------------- helpers ---------------------------------------------------
DINL uint32_t smem_u32(const void* p) {
    uint32_t a;
    asm("{ .reg .u64 t; cvta.to.shared.u64 t, %1; cvt.u32.u64 %0, t; }"
        : "=r"(a) : "l"(p));
    return a;
}
// SW128 swizzle for 128-byte rows (Swizzle<3,4,3>)
DINL uint32_t swz(uint32_t x) { return x ^ ((x >> 3) & 0x70); }

DINL void cp16(uint32_t dst, const void* src) {
    asm volatile("cp.async.cg.shared.global [%0], [%1], 16;"
                 :: "r"(dst), "l"(src) : "memory");
}
#define CP_COMMIT() asm volatile("cp.async.commit_group;" ::: "memory")
#define CP_WAIT0()  asm volatile("cp.async.wait_group 0;" ::: "memory")

DINL void ldm4(uint32_t* r, uint32_t addr) {
    asm volatile("ldmatrix.sync.aligned.m8n8.x4.shared.b16 {%0,%1,%2,%3}, [%4];"
                 : "=r"(r[0]), "=r"(r[1]), "=r"(r[2]), "=r"(r[3]) : "r"(addr));
}
DINL void mma16816(float* c, const uint32_t* a, uint32_t b0, uint32_t b1) {
    asm volatile(
        "mma.sync.aligned.m16n8k16.row.col.f32.f16.f16.f32 "
        "{%0,%1,%2,%3}, {%4,%5,%6,%7}, {%8,%9}, {%0,%1,%2,%3};"
        : "+f"(c[0]), "+f"(c[1]), "+f"(c[2]), "+f"(c[3])
        : "r"(a[0]), "r"(a[1]), "r"(a[2]), "r"(a[3]), "r"(b0), "r"(b1));
}

// ============================================================================
// Kernel 1 (fused prep): blocks [0, SPLIT_BLOCKS) convert x -> fp16;
// blocks [SPLIT_BLOCKS, +BUILD_BLOCKS) build W_eff = W + A@B -> fp16.
// ============================================================================
__global__ void __launch_bounds__(256) prep_kernel(
    const float* __restrict__ x,
    const float* __restrict__ weight,   // [N,K] row-major
    const float* __restrict__ A,        // [K,RANK]
    const float* __restrict__ B)        // [RANK,N]
{
    __shared__ float As[64][RANK];
    __shared__ float Bs[RANK][256];

    int tid = threadIdx.x;

    if (blockIdx.x < SPLIT_BLOCKS) {
        size_t e = ((size_t)blockIdx.x * 256 + tid) * 8;
        const float4* p = reinterpret_cast<const float4*>(x + e);
        float4 v0 = p[0], v1 = p[1];
        float vv[8] = {v0.x, v0.y, v0.z, v0.w, v1.x, v1.y, v1.z, v1.w};
        __half h[8];
#pragma unroll
        for (int i = 0; i < 8; i++) h[i] = __float2half_rn(vv[i]);
        *reinterpret_cast<uint4*>(g_xh + e) = *reinterpret_cast<uint4*>(h);
        return;
    }

    int bid2 = blockIdx.x - SPLIT_BLOCKS;
    int kblk = bid2 & 63, nblk = bid2 >> 6;
    int d0 = kblk * 64, o0 = nblk * 256;

    reinterpret_cast<float4*>(&As[0][0])[tid] =
        reinterpret_cast<const float4*>(A + (size_t)d0 * RANK)[tid];
#pragma unroll
    for (int r = 0; r < RANK; r++)
        Bs[r][tid] = B[(size_t)r * N_DIM + o0 + tid];
    __syncthreads();

    int o = o0 + tid;
    const float* wrow = weight + (size_t)o * K_DIM + d0;

#pragma unroll 1
    for (int dc = 0; dc < 64; dc += 8) {
        float4 wa = reinterpret_cast<const float4*>(wrow + dc)[0];
        float4 wb = reinterpret_cast<const float4*>(wrow + dc)[1];
        float w[8] = {wa.x, wa.y, wa.z, wa.w, wb.x, wb.y, wb.z, wb.w};
        __half h[8];
#pragma unroll
        for (int i = 0; i < 8; i++) {
            float s = 0.f;
#pragma unroll
            for (int r = 0; r < RANK; r++) s += As[dc + i][r] * Bs[r][tid];
            h[i] = __float2half_rn(w[i] + s);
        }
        *reinterpret_cast<uint4*>(g_wh + (size_t)o * K_DIM + d0 + dc) =
            *reinterpret_cast<uint4*>(h);
    }
}

// ============================================================================
// Kernel 2: GEMM. CTA = 128x128, 128 thr (4 warps, 64x64 tiles), 2 CTAs/SM,
// BK=64, 3-stage cp.async (4 cp16/kc, issued after first MMA group),
// fp16 mma -> fp32 accum, [8 MMA | 2 ldm4] interleave, iter-end wait+sync.
// ============================================================================
__global__ void __launch_bounds__(128, 2)
gemm_kernel(const float* __restrict__ bias, float* __restrict__ out)
{
    extern __shared__ __align__(1024) char smem[];
    const uint32_t sbase = smem_u32(smem);

    const int tid  = threadIdx.x;
    const int wid  = tid >> 5;
    const int lane = tid & 31;

    // grouped ordering: groups of (8 m) x (32 n) = 256 CTAs
    const int bid  = blockIdx.x;
    const int grp  = bid >> 8;
    const int mblk = grp * 8 + ((bid >> 5) & 7);
    const int nblk = bid & 31;

    // anti-phase offset for co-resident CTA pairs (kept from R15)
    if (((bid / 152) & 1) != 0) {
        unsigned long long t0 = clock64();
        while (clock64() - t0 < PHASE_DELAY) { }
    }

    const int m_base = (wid >> 1) * 64;   // 0 or 64
    const int n_base = (wid & 1) * 64;    // 0 or 64

    // ldmatrix lane-relative mapping
    const int r16   = (lane & 7) + ((lane >> 3) & 1) * 8;
    const uint32_t cx = (uint32_t)(lane >> 4) << 4;   // chalf*16 (bit 4)

    // per-thread swizzle bases for ldmatrix: addr = (stage+base) ^ (acol*16)
    uint32_t base_x[4], base_w[4];
#pragma unroll
    for (int mt = 0; mt < 4; mt++) {
        uint32_t row = (uint32_t)(m_base + mt * 16 + r16);
        base_x[mt] = OFF_XH + row * 128 + ((row << 4) & 0x70);
    }
#pragma unroll
    for (int t = 0; t < 4; t++) {
        uint32_t row = (uint32_t)(n_base + t * 16 + r16);
        base_w[t] = OFF_WH + row * 128 + ((row << 4) & 0x70);
    }

    // ---------------- strength-reduced loader state (128 threads) ----------
    const int lrow = tid >> 3;            // 0..15
    const int lcol = (tid & 7) * 8;
    const __half* px = g_xh + (size_t)(mblk * BM + lrow) * K_DIM + lcol;
    const __half* pw = g_wh + (size_t)(nblk * BN + lrow) * K_DIM + lcol;
    const uint32_t sox = OFF_XH + swz((uint32_t)(lrow * 128 + (tid & 7) * 16));
    const uint32_t sow = OFF_WH + swz((uint32_t)(lrow * 128 + (tid & 7) * 16));

    float acc[4][8][4];
#pragma unroll
    for (int mt = 0; mt < 4; mt++)
#pragma unroll
        for (int nt = 0; nt < 8; nt++)
#pragma unroll
            for (int q = 0; q < 4; q++) acc[mt][nt][q] = 0.f;

    // prologue: stages 0 and 1 fully loaded (burst is fine here)
#pragma unroll
    for (int s = 0; s < 2; s++) {
        uint32_t db = sbase + s * STAGE_B;
        const __half* pxs = px + s * BK;
        const __half* pws = pw + s * BK;
#pragma unroll
        for (int i = 0; i < 8; i++)
            cp16(db + sox + i * 2048, pxs + (size_t)i * 16 * K_DIM);
#pragma unroll
        for (int i = 0; i < 8; i++)
            cp16(db + sow + i * 2048, pws + (size_t)i * 16 * K_DIM);
        CP_COMMIT();
    }
    px += 2 * BK;  pw += 2 * BK;
    CP_WAIT0();
    __syncthreads();

    uint32_t xa[2][4][4], wf[2][4][4];
#pragma unroll
    for (int mt = 0; mt < 4; mt++) ldm4(xa[0][mt], (sbase + base_x[mt]) ^ cx);
#pragma unroll
    for (int t = 0; t < 4; t++)  ldm4(wf[0][t],  (sbase + base_w[t]) ^ cx);

    int s_cur = 0, s_nxt = 1, s_ld = 2;   // stage indices (mod 3)

#pragma unroll 1
    for (int it = 0; it < NKI; it++) {
        const uint32_t sb  = sbase + s_cur * STAGE_B;
        const uint32_t sbn = sbase + s_nxt * STAGE_B;
        const uint32_t db  = sbase + s_ld  * STAGE_B;
        const bool ldv = (it + 2 < NKI);

#pragma unroll
        for (int kc = 0; kc < 4; kc++) {
            const int cur = kc & 1, nxt = cur ^ 1;
            // frag prefetch source: next kc in this stage, or kc0 of s_nxt
            const uint32_t psb  = (kc < 3) ? sb : sbn;
            const uint32_t pxor = (kc < 3) ? ((uint32_t)((kc + 1) << 5) | cx) : cx;

            // 4 groups of [8 MMA | 2 prefetch ldm4]; the 4 stage-load cp16s
            // for this kc are issued AFTER group 0's MMAs (critical path
            // out of the barrier starts with MMAs, LSU pressure spread).
#pragma unroll
            for (int g = 0; g < 4; g++) {
                const int mt = g;
#pragma unroll
                for (int nt = 0; nt < 8; nt++)
                    mma16816(acc[mt][nt], xa[cur][mt],
                             wf[cur][nt >> 1][nt & 1], wf[cur][nt >> 1][(nt & 1) + 2]);

                if (g == 0 && ldv) {
                    cp16(db + sox + (2 * kc)     * 2048, px + (size_t)(2 * kc)     * 16 * K_DIM);
                    cp16(db + sox + (2 * kc + 1) * 2048, px + (size_t)(2 * kc + 1) * 16 * K_DIM);
                    cp16(db + sow + (2 * kc)     * 2048, pw + (size_t)(2 * kc)     * 16 * K_DIM);
                    cp16(db + sow + (2 * kc + 1) * 2048, pw + (size_t)(2 * kc + 1) * 16 * K_DIM);
                }

                if (g < 2) {
                    ldm4(xa[nxt][2 * g + 0], (psb + base_x[2 * g + 0]) ^ pxor);
                    ldm4(xa[nxt][2 * g + 1], (psb + base_x[2 * g + 1]) ^ pxor);
                } else {
                    ldm4(wf[nxt][2 * (g - 2) + 0], (psb + base_w[2 * (g - 2) + 0]) ^ pxor);
                    ldm4(wf[nxt][2 * (g - 2) + 1], (psb + base_w[2 * (g - 2) + 1]) ^ pxor);
                }
            }
        }
        CP_COMMIT();     // one group per iter, same wait semantics as R11

        // wait for the group committed THIS iter (stage it+2), then barrier
        // before overwriting s_cur next iter. Identical to R11/R15.
        CP_WAIT0();
        __syncthreads();

        px += BK;  pw += BK;
        int t0 = s_cur; s_cur = s_nxt; s_nxt = s_ld; s_ld = t0;
    }

    // ---------------- epilogue: bias add + fp32 store ----------------
    const int gm = mblk * BM + m_base;
    const int gn = nblk * BN + n_base;
#pragma unroll
    for (int nt = 0; nt < 8; nt++) {
        int col = gn + nt * 8 + 2 * (lane & 3);
        float2 bv = *reinterpret_cast<const float2*>(bias + col);
#pragma unroll
        for (int mt = 0; mt < 4; mt++) {
            int row0 = gm + mt * 16 + (lane >> 2);
            float2 v0 = {acc[mt][nt][0] + bv.x, acc[mt][nt][1] + bv.y};
            float2 v1 = {acc[mt][nt][2] + bv.x, acc[mt][nt][3] + bv.y};
            *reinterpret_cast<float2*>(out + (size_t)row0 * N_DIM + col) = v0;
            *reinterpret_cast<float2*>(out + (size_t)(row0 + 8) * N_DIM + col) = v1;
        }
    }
}

// ============================================================================
// Launch
// ============================================================================
extern "C" void kernel_launch(void* const* d_in, const int* in_sizes, int n_in,
                              void* d_out, int out_size)
{
    const float* x      = (const float*)d_in[0];
    const float* A      = (const float*)d_in[1];
    const float* B      = (const float*)d_in[2];
    const float* weight = (const float*)d_in[3];
    const float* bias   = (const float*)d_in[4];
    float* out = (float*)d_out;

    cudaFuncSetAttribute(gemm_kernel,
                         cudaFuncAttributeMaxDynamicSharedMemorySize, SMEM_BYTES);

    prep_kernel<<<SPLIT_BLOCKS + BUILD_BLOCKS, 256>>>(x, weight, A, B);
    gemm_kernel<<<(M_DIM / BM) * (N_DIM / BN), 128, SMEM_BYTES>>>(bias, out);
}

// round 17
// speedup vs baseline: 1.0373x; 1.0373x over previous
#include <cuda_runtime.h>
#include <cuda_fp16.h>
#include <cstdint>

// ============================================================================
// LoRALayer: out[16384,4096] = x[16384,4096] @ W_eff^T + bias
//   W_eff[o,d] = weight[o,d] + sum_r A[d,r]*B[r,o]
// sm_103 (non-'a' PTX): legacy mma.sync fp16 HMMA, fp32 accum, 1 pass.
// R17: R15 (best, 1205us) with ONE isolated change: the per-iter wait+sync
// moves from iter-end to just before kc3, with wait_group 0 -> 1.
// Mechanism: every warp crosses the barrier holding 32 register-resident
// MMAs (kc3), so the SM's tensor pipe never fully drains at the sync; the
// relaxed wait gives each cp.async stage ~2 iterations of slack.
// (R16 proved the spread-loads half of R12 caused its regression; the
// barrier move was neutral-positive even when handicapped.)
// ============================================================================

#define DINL __device__ __forceinline__

constexpr int M_DIM = 16384;
constexpr int N_DIM = 4096;
constexpr int K_DIM = 4096;
constexpr int RANK  = 16;

constexpr int BM = 128;
constexpr int BN = 128;
constexpr int BK = 64;
constexpr int NKI = K_DIM / BK;           // 64 k-iterations
constexpr int STAGES = 3;

// per-stage smem (fp16, 128B rows): XH[128][64] WH[128][64]
constexpr int OFF_XH = 0;
constexpr int OFF_WH = 16384;
constexpr int STAGE_B = 32768;
constexpr int SMEM_BYTES = STAGES * STAGE_B;   // 98304 (occ 2 ok)

constexpr int SPLIT_BLOCKS = (int)(((size_t)M_DIM * K_DIM) / 8 / 256);  // 32768
constexpr int BUILD_BLOCKS = (K_DIM / 64) * (N_DIM / 256);              // 1024

constexpr unsigned long long PHASE_DELAY = 1280;

// ---------------- scratch (device globals; no runtime allocation) ----------
__device__ __half g_xh[(size_t)M_DIM * K_DIM];
__device__ __half g_wh[(size_t)N_DIM * K_DIM];

// ---------------- helpers ---------------------------------------------------
DINL uint32_t smem_u32(const void* p) {
    uint32_t a;
    asm("{ .reg .u64 t; cvta.to.shared.u64 t, %1; cvt.u32.u64 %0, t; }"
        : "=r"(a) : "l"(p));
    return a;
}
// SW128 swizzle for 128-byte rows (Swizzle<3,4,3>)
DINL uint32_t swz(uint32_t x) { return x ^ ((x >> 3) & 0x70); }

DINL void cp16(uint32_t dst, const void* src) {
    asm volatile("cp.async.cg.shared.global [%0], [%1], 16;"
                 :: "r"(dst), "l"(src) : "memory");
}
#define CP_COMMIT() asm volatile("cp.async.commit_group;" ::: "memory")
#define CP_WAIT1()  asm volatile("cp.async.wait_group 1;" ::: "memory")

DINL void ldm4(uint32_t* r, uint32_t addr) {
    asm volatile("ldmatrix.sync.aligned.m8n8.x4.shared.b16 {%0,%1,%2,%3}, [%4];"
                 : "=r"(r[0]), "=r"(r[1]), "=r"(r[2]), "=r"(r[3]) : "r"(addr));
}
DINL void mma16816(float* c, const uint32_t* a, uint32_t b0, uint32_t b1) {
    asm volatile(
        "mma.sync.aligned.m16n8k16.row.col.f32.f16.f16.f32 "
        "{%0,%1,%2,%3}, {%4,%5,%6,%7}, {%8,%9}, {%0,%1,%2,%3};"
        : "+f"(c[0]), "+f"(c[1]), "+f"(c[2]), "+f"(c[3])
        : "r"(a[0]), "r"(a[1]), "r"(a[2]), "r"(a[3]), "r"(b0), "r"(b1));
}

// ============================================================================
// Kernel 1 (fused prep): blocks [0, SPLIT_BLOCKS) convert x -> fp16;
// blocks [SPLIT_BLOCKS, +BUILD_BLOCKS) build W_eff = W + A@B -> fp16.
// ============================================================================
__global__ void __launch_bounds__(256) prep_kernel(
    const float* __restrict__ x,
    const float* __restrict__ weight,   // [N,K] row-major
    const float* __restrict__ A,        // [K,RANK]
    const float* __restrict__ B)        // [RANK,N]
{
    __shared__ float As[64][RANK];
    __shared__ float Bs[RANK][256];

    int tid = threadIdx.x;

    if (blockIdx.x < SPLIT_BLOCKS) {
        size_t e = ((size_t)blockIdx.x * 256 + tid) * 8;
        const float4* p = reinterpret_cast<const float4*>(x + e);
        float4 v0 = p[0], v1 = p[1];
        float vv[8] = {v0.x, v0.y, v0.z, v0.w, v1.x, v1.y, v1.z, v1.w};
        __half h[8];
#pragma unroll
        for (int i = 0; i < 8; i++) h[i] = __float2half_rn(vv[i]);
        *reinterpret_cast<uint4*>(g_xh + e) = *reinterpret_cast<uint4*>(h);
        return;
    }

    int bid2 = blockIdx.x - SPLIT_BLOCKS;
    int kblk = bid2 & 63, nblk = bid2 >> 6;
    int d0 = kblk * 64, o0 = nblk * 256;

    reinterpret_cast<float4*>(&As[0][0])[tid] =
        reinterpret_cast<const float4*>(A + (size_t)d0 * RANK)[tid];
#pragma unroll
    for (int r = 0; r < RANK; r++)
        Bs[r][tid] = B[(size_t)r * N_DIM + o0 + tid];
    __syncthreads();

    int o = o0 + tid;
    const float* wrow = weight + (size_t)o * K_DIM + d0;

#pragma unroll 1
    for (int dc = 0; dc < 64; dc += 8) {
        float4 wa = reinterpret_cast<const float4*>(wrow + dc)[0];
        float4 wb = reinterpret_cast<const float4*>(wrow + dc)[1];
        float w[8] = {wa.x, wa.y, wa.z, wa.w, wb.x, wb.y, wb.z, wb.w};
        __half h[8];
#pragma unroll
        for (int i = 0; i < 8; i++) {
            float s = 0.f;
#pragma unroll
            for (int r = 0; r < RANK; r++) s += As[dc + i][r] * Bs[r][tid];
            h[i] = __float2half_rn(w[i] + s);
        }
        *reinterpret_cast<uint4*>(g_wh + (size_t)o * K_DIM + d0 + dc) =
            *reinterpret_cast<uint4*>(h);
    }
}

// ============================================================================
// Kernel 2: GEMM. CTA = 128x128, 128 thr (4 warps, 64x64 tiles), 2 CTAs/SM,
// BK=64, 3-stage cp.async (burst at iter start), fp16 mma -> fp32 accum,
// [8 MMA | 2 ldm4] interleave, wait_group1+sync BEFORE kc3 (not iter end).
// ============================================================================
__global__ void __launch_bounds__(128, 2)
gemm_kernel(const float* __restrict__ bias, float* __restrict__ out)
{
    extern __shared__ __align__(1024) char smem[];
    const uint32_t sbase = smem_u32(smem);

    const int tid  = threadIdx.x;
    const int wid  = tid >> 5;
    const int lane = tid & 31;

    // grouped ordering: groups of (8 m) x (32 n) = 256 CTAs
    const int bid  = blockIdx.x;
    const int grp  = bid >> 8;
    const int mblk = grp * 8 + ((bid >> 5) & 7);
    const int nblk = bid & 31;

    // anti-phase offset for co-resident CTA pairs (kept from R15)
    if (((bid / 152) & 1) != 0) {
        unsigned long long t0 = clock64();
        while (clock64() - t0 < PHASE_DELAY) { }
    }

    const int m_base = (wid >> 1) * 64;   // 0 or 64
    const int n_base = (wid & 1) * 64;    // 0 or 64

    // ldmatrix lane-relative mapping
    const int r16   = (lane & 7) + ((lane >> 3) & 1) * 8;
    const uint32_t cx = (uint32_t)(lane >> 4) << 4;   // chalf*16 (bit 4)

    // per-thread swizzle bases for ldmatrix: addr = (stage+base) ^ (acol*16)
    uint32_t base_x[4], base_w[4];
#pragma unroll
    for (int mt = 0; mt < 4; mt++) {
        uint32_t row = (uint32_t)(m_base + mt * 16 + r16);
        base_x[mt] = OFF_XH + row * 128 + ((row << 4) & 0x70);
    }
#pragma unroll
    for (int t = 0; t < 4; t++) {
        uint32_t row = (uint32_t)(n_base + t * 16 + r16);
        base_w[t] = OFF_WH + row * 128 + ((row << 4) & 0x70);
    }

    // ---------------- strength-reduced loader state (128 threads) ----------
    const int lrow = tid >> 3;            // 0..15
    const int lcol = (tid & 7) * 8;
    const __half* px = g_xh + (size_t)(mblk * BM + lrow) * K_DIM + lcol;
    const __half* pw = g_wh + (size_t)(nblk * BN + lrow) * K_DIM + lcol;
    const uint32_t sox = OFF_XH + swz((uint32_t)(lrow * 128 + (tid & 7) * 16));
    const uint32_t sow = OFF_WH + swz((uint32_t)(lrow * 128 + (tid & 7) * 16));

    auto load_stage = [&](uint32_t db, const __half* pxk, const __half* pwk,
                          bool valid) {
        if (valid) {
#pragma unroll
            for (int i = 0; i < 8; i++)
                cp16(db + sox + i * 2048, pxk + (size_t)i * 16 * K_DIM);
#pragma unroll
            for (int i = 0; i < 8; i++)
                cp16(db + sow + i * 2048, pwk + (size_t)i * 16 * K_DIM);
        }
        CP_COMMIT();
    };

    float acc[4][8][4];
#pragma unroll
    for (int mt = 0; mt < 4; mt++)
#pragma unroll
        for (int nt = 0; nt < 8; nt++)
#pragma unroll
            for (int q = 0; q < 4; q++) acc[mt][nt][q] = 0.f;

    // prologue: stages 0 and 1 fully loaded
    load_stage(sbase,           px,      pw,      true);
    load_stage(sbase + STAGE_B, px + BK, pw + BK, true);
    px += 2 * BK;  pw += 2 * BK;
    {   // both prologue stages must be complete before first frag loads
        asm volatile("cp.async.wait_group 0;" ::: "memory");
    }
    __syncthreads();

    uint32_t xa[2][4][4], wf[2][4][4];
#pragma unroll
    for (int mt = 0; mt < 4; mt++) ldm4(xa[0][mt], (sbase + base_x[mt]) ^ cx);
#pragma unroll
    for (int t = 0; t < 4; t++)  ldm4(wf[0][t],  (sbase + base_w[t]) ^ cx);

    int s_cur = 0, s_nxt = 1, s_ld = 2;   // stage indices (mod 3)

#pragma unroll 1
    for (int it = 0; it < NKI; it++) {
        // burst-load stage it+2 at iter start (proven best placement)
        load_stage(sbase + s_ld * STAGE_B, px, pw, it + 2 < NKI);
        px += BK;  pw += BK;

        const uint32_t sb  = sbase + s_cur * STAGE_B;
        const uint32_t sbn = sbase + s_nxt * STAGE_B;

#pragma unroll
        for (int kc = 0; kc < 4; kc++) {
            const int cur = kc & 1, nxt = cur ^ 1;
            // prefetch source: next kc in this stage, or kc0 of next stage
            const uint32_t psb  = (kc < 3) ? sb : sbn;
            const uint32_t pxor = (kc < 3) ? ((uint32_t)((kc + 1) << 5) | cx) : cx;

            // mid-iter sync: all s_cur reads ended at kc2's prefetch; kc3
            // needs stage s_nxt complete = all-but-last committed group
            // (wait_group 1: stage it+2's load stays in flight). Each warp
            // crosses the barrier holding 32 MMAs -> no tensor-pipe drain.
            if (kc == 3) {
                CP_WAIT1();
                __syncthreads();
            }

            // 4 groups of [8 MMA | 2 prefetch ldm4]
#pragma unroll
            for (int g = 0; g < 4; g++) {
                const int mt = g;
#pragma unroll
                for (int nt = 0; nt < 8; nt++)
                    mma16816(acc[mt][nt], xa[cur][mt],
                             wf[cur][nt >> 1][nt & 1], wf[cur][nt >> 1][(nt & 1) + 2]);

                if (g < 2) {
                    ldm4(xa[nxt][2 * g + 0], (psb + base_x[2 * g + 0]) ^ pxor);
                    ldm4(xa[nxt][2 * g + 1], (psb + base_x[2 * g + 1]) ^ pxor);
                } else {
                    ldm4(wf[nxt][2 * (g - 2) + 0], (psb + base_w[2 * (g - 2) + 0]) ^ pxor);
                    ldm4(wf[nxt][2 * (g - 2) + 1], (psb + base_w[2 * (g - 2) + 1]) ^ pxor);
                }
            }
        }
        // no iter-end wait/sync: the kc3 barrier of THIS iter already
        // orders next iter's buffer overwrite (writes target the buffer
        // whose last reads were kc2, before this iter's barrier).

        int t0 = s_cur; s_cur = s_nxt; s_nxt = s_ld; s_ld = t0;
    }

    // ---------------- epilogue: bias add + fp32 store ----------------
    const int gm = mblk * BM + m_base;
    const int gn = nblk * BN + n_base;
#pragma unroll
    for (int nt = 0; nt < 8; nt++) {
        int col = gn + nt * 8 + 2 * (lane & 3);
        float2 bv = *reinterpret_cast<const float2*>(bias + col);
#pragma unroll
        for (int mt = 0; mt < 4; mt++) {
            int row0 = gm + mt * 16 + (lane >> 2);
            float2 v0 = {acc[mt][nt][0] + bv.x, acc[mt][nt][1] + bv.y};
            float2 v1 = {acc[mt][nt][2] + bv.x, acc[mt][nt][3] + bv.y};
            *reinterpret_cast<float2*>(out + (size_t)row0 * N_DIM + col) = v0;
            *reinterpret_cast<float2*>(out + (size_t)(row0 + 8) * N_DIM + col) = v1;
        }
    }
}

// ============================================================================
// Launch
// ============================================================================
extern "C" void kernel_launch(void* const* d_in, const int* in_sizes, int n_in,
                              void* d_out, int out_size)
{
    const float* x      = (const float*)d_in[0];
    const float* A      = (const float*)d_in[1];
    const float* B      = (const float*)d_in[2];
    const float* weight = (const float*)d_in[3];
    const float* bias   = (const float*)d_in[4];
    float* out = (float*)d_out;

    cudaFuncSetAttribute(gemm_kernel,
                         cudaFuncAttributeMaxDynamicSharedMemorySize, SMEM_BYTES);

    prep_kernel<<<SPLIT_BLOCKS + BUILD_BLOCKS, 256>>>(x, weight, A, B);
    gemm_kernel<<<(M_DIM / BM) * (N_DIM / BN), 128, SMEM_BYTES>>>(bias, out);
}